// round 17
// baseline (speedup 1.0000x reference)
#include <cuda_runtime.h>
#include <cstdint>

// Problem constants
#define BATCH   16
#define TLEN    4096
#define DIMX    256
#define HID     128
#define G3      384
#define NLAYER  3
#define MROWS   (BATCH * TLEN)      // 65536

// Persistent-kernel structure
#define NBLK    148
#define RECB    32
#define GEMB    (NBLK - RECB)       // 116
#define NTHR    768

// GEMM tiling
#define BM      128
#define BN      96
#define BK      16
#define NT_PER  (G3 / BN)           // 4
#define NCHUNK  (TLEN / BM)         // 32
#define TILES_PER_LAYER (2 * BATCH * NCHUNK * NT_PER)   // 4096

// -------- scratch (device globals; no runtime allocation allowed) ----------
__device__ float g_xgA[(size_t)2 * MROWS * G3];
__device__ float g_xgB[(size_t)2 * MROWS * G3];
__device__ float g_yA[(size_t)MROWS * DIMX];
__device__ float g_yB[(size_t)MROWS * DIMX];
__device__ unsigned g_fwdsteps[NLAYER][BATCH];
__device__ unsigned g_bwdsteps[NLAYER][BATCH];
__device__ unsigned g_xgready[NLAYER][2][BATCH][NCHUNK];

// ---------------- f32x2 packed helpers (Blackwell sm_103a) -----------------
__device__ __forceinline__ unsigned long long pk2(float lo, float hi) {
    unsigned long long r;
    asm("mov.b64 %0, {%1, %2};" : "=l"(r) : "f"(lo), "f"(hi));
    return r;
}
__device__ __forceinline__ void up2(unsigned long long v, float& lo, float& hi) {
    asm("mov.b64 {%0, %1}, %2;" : "=f"(lo), "=f"(hi) : "l"(v));
}
__device__ __forceinline__ unsigned long long fma2(unsigned long long a,
                                                   unsigned long long b,
                                                   unsigned long long c) {
    unsigned long long d;
    asm("fma.rn.f32x2 %0, %1, %2, %3;" : "=l"(d) : "l"(a), "l"(b), "l"(c));
    return d;
}
__device__ __forceinline__ unsigned long long fadd2(unsigned long long a,
                                                    unsigned long long b) {
    unsigned long long d;
    asm("add.rn.f32x2 %0, %1, %2;" : "=l"(d) : "l"(a), "l"(b));
    return d;
}
__device__ __forceinline__ float ex2f(float x) {
    float y; asm("ex2.approx.f32 %0, %1;" : "=f"(y) : "f"(x)); return y;
}
__device__ __forceinline__ float rcpf(float x) {
    float y; asm("rcp.approx.f32 %0, %1;" : "=f"(y) : "f"(x)); return y;
}
__device__ __forceinline__ float sigmf(float x) {
    return rcpf(1.0f + ex2f(x * -1.4426950408889634f));
}
__device__ __forceinline__ float tanhf_(float x) {
    return fmaf(-2.0f, rcpf(1.0f + ex2f(x * 2.8853900817779268f)), 1.0f);
}
__device__ __forceinline__ unsigned ldv(const unsigned* p) {
    return *(volatile const unsigned*)p;
}

// -------------------------- flag reset kernel ------------------------------
__global__ void reset_flags() {
    int i = blockIdx.x * blockDim.x + threadIdx.x;
    unsigned* r = &g_xgready[0][0][0][0];
    const int nr = NLAYER * 2 * BATCH * NCHUNK;
    if (i < nr) r[i] = 0;
    if (i < NLAYER * BATCH) {
        (&g_fwdsteps[0][0])[i] = 0;
        (&g_bwdsteps[0][0])[i] = 0;
    }
}

// --------------------------- one GRU timestep ------------------------------
// Two threads per gate column: even lane sums h[0:64), odd lane h[64:128);
// combined via shfl.xor 1. Even lane performs activations/stores.
__device__ __forceinline__ void gru_step(
    const float*& xp, float& x0, float*& yp, float& hp,
    long sstride, long ystride, long pf_off,
    const unsigned long long* w2, unsigned long long binit,
    bool even, int gate, int jj,
    const ulonglong2* h2, float* sh_h, float* sh_g)
{
    float xn = __ldg(xp + pf_off);   // x for next step (distance-1)

    // half matvec: 64 h values, 32 fma2
    unsigned long long a0 = binit, a1 = 0ULL;
#pragma unroll
    for (int i = 0; i < 16; i++) {
        ulonglong2 hv = h2[i];
        a0 = fma2(hv.x, w2[2 * i],     a0);
        a1 = fma2(hv.y, w2[2 * i + 1], a1);
    }
    a0 = fadd2(a0, a1);
    float lo_, hi_;
    up2(a0, lo_, hi_);
    float part = lo_ + hi_;
    const float q = part + __shfl_xor_sync(0xFFFFFFFFu, part, 1);

    if (even & (gate < 2)) sh_g[gate * HID + jj] = sigmf(x0 + q);
    __syncthreads();

    if (even & (gate == 2)) {
        float r_ = sh_g[jj];
        float z_ = sh_g[HID + jj];
        float n_ = tanhf_(fmaf(r_, q, x0));
        float hn = fmaf(z_, hp - n_, n_);
        hp = hn;
        sh_h[jj] = hn;
        *yp = hn;
    }
    __syncthreads();

    x0 = xn;
    xp += sstride;
    yp += ystride;
}

// ------------------------- persistent fused kernel -------------------------
__global__ void __launch_bounds__(NTHR, 1)
fused_birnn(const float* __restrict__ xin,
            const float* __restrict__ Wi,   // [3][2][256][384]
            const float* __restrict__ Wh,   // [3][2][128][384]
            const float* __restrict__ bh,   // [3][2][384]
            float* __restrict__ out) {
    __shared__ __align__(16) float sh_As[2][BK][BM + 4];
    __shared__ __align__(16) unsigned long long sh_Bs[2][BK][BN];
    __shared__ __align__(16) float sh_h[HID];
    __shared__ __align__(16) float sh_g[2 * HID];   // [r | z]

    const int tid = threadIdx.x;

    if (blockIdx.x < RECB) {
        // ================= RECURRENCE ROLE (blocks 0..31) ==================
        const int d = blockIdx.x >> 4;
        const int b = blockIdx.x & 15;
        const int col = tid >> 1;        // gate column 0..383
        const int half = tid & 1;        // 0: h[0:64), 1: h[64:128)
        const bool even = (half == 0);
        const int gate = col >> 7;
        const int jj = col & 127;
        const int dt = d ? -1 : 1;
        const long sstride = (long)dt * G3;
        const long ystride = (long)dt * DIMX;
        const ulonglong2* h2 = (const ulonglong2*)sh_h + half * 16;

        for (int l = 0; l < NLAYER; l++) {
            const float* Wd = Wh + (size_t)(l * 2 + d) * HID * G3;
            // bias folded into even lane's accumulator init
            const unsigned long long binit =
                even ? pk2(bh[(l * 2 + d) * G3 + col], 0.0f) : 0ULL;
            const float* xgbuf = (l == 1) ? g_xgB : g_xgA;
            const float* xgb = xgbuf + ((size_t)d * MROWS + (size_t)b * TLEN) * G3;
            float* yo = (l == 0) ? g_yA : (l == 1) ? g_yB : out;
            const unsigned* rdy = &g_xgready[l][d][b][0];

            // this thread's 32 weight pairs (h rows half*64 .. half*64+63)
            unsigned long long w2[32];
#pragma unroll
            for (int i = 0; i < 32; i++)
                w2[i] = pk2(Wd[(half * 64 + 2 * i) * G3 + col],
                            Wd[(half * 64 + 2 * i + 1) * G3 + col]);

            if (tid < HID) sh_h[tid] = 0.0f;

            // wait for first consumed chunk
            {
                const int c0 = d ? (NCHUNK - 1) : 0;
                if (tid == 0) {
                    while (ldv(&rdy[c0]) < NT_PER) __nanosleep(64);
                }
            }
            __syncthreads();
            __threadfence();

            const int t0 = d ? (TLEN - 1) : 0;
            const float* xp = xgb + (size_t)t0 * G3 + col;
            float x0 = __ldg(xp);
            float* yp = yo + (size_t)b * TLEN * DIMX + (size_t)t0 * DIMX
                        + d * HID + jj;
            float hp = 0.0f;
            unsigned done = 0;

            for (int c = 0; c < NCHUNK; c++) {
                // 127 steps whose distance-1 prefetch stays inside chunk c
                for (int u = 0; u < 127; u++) {
                    gru_step(xp, x0, yp, hp, sstride, ystride, sstride,
                             w2, binit, even, gate, jj, h2, sh_h, sh_g);
                }
                if (c < NCHUNK - 1) {
                    // last step prefetches into chunk c+1: wait first
                    const int cn = d ? (NCHUNK - 2 - c) : (c + 1);
                    if (tid == 0) {
                        while (ldv(&rdy[cn]) < NT_PER) __nanosleep(64);
                    }
                    __syncthreads();
                    __threadfence();
                    gru_step(xp, x0, yp, hp, sstride, ystride, sstride,
                             w2, binit, even, gate, jj, h2, sh_h, sh_g);
                } else {
                    gru_step(xp, x0, yp, hp, sstride, ystride, 0,
                             w2, binit, even, gate, jj, h2, sh_h, sh_g);
                }
                done += BM;
                if (tid == 0) {
                    __threadfence();
                    *(volatile unsigned*)(d ? &g_bwdsteps[l][b]
                                            : &g_fwdsteps[l][b]) = done;
                }
            }
        }
    } else {
        // =================== GEMM ROLE (blocks 32..147) ====================
        const int gid = blockIdx.x - RECB;
        // compute mapping: 768 threads, 4x4 outputs each
        const int ty4 = (tid / 24) * 4;      // rows ty4..ty4+3 (0..124)
        const int tx4 = (tid % 24) * 4;      // cols tx4..tx4+3 (0..92)
        // A loader: tid<512 -> arow 0..127, ak in {0,4,8,12}
        const int arow = tid >> 2;
        const int ak = (tid & 3) << 2;
        // B loader: tid<384 -> brow 0..15, bc multiples of 4
        const int brow = tid / 24;
        const int bc = (tid % 24) * 4;

        for (int l = 0; l < NLAYER; l++) {
            const float* Asrc = (l == 0) ? xin : (l == 1) ? g_yA : g_yB;
            float* xgdst = (l == 1) ? g_xgB : g_xgA;
            const float* Wl = Wi + (size_t)l * 2 * DIMX * G3;

            for (int rank = gid; rank < TILES_PER_LAYER; rank += GEMB) {
                const int o = rank >> 7;
                const int rem = rank & 127;
                const int dir = rem >> 6;
                const int b = (rem >> 2) & 15;
                const int nt = rem & 3;
                int ci;
                if (l == 0)
                    ci = (o & 1) ? (NCHUNK - 1 - (o >> 1)) : (o >> 1);
                else
                    ci = (o & 1) ? (NCHUNK / 2 + (o >> 1))
                                 : (NCHUNK / 2 - 1 - (o >> 1));

                if (l > 0) {
                    if (tid == 0) {
                        unsigned needf = (unsigned)((ci + 1) * BM);
                        unsigned needb = (unsigned)(TLEN - ci * BM);
                        while (ldv(&g_fwdsteps[l - 1][b]) < needf) __nanosleep(128);
                        while (ldv(&g_bwdsteps[l - 1][b]) < needb) __nanosleep(128);
                    }
                    __syncthreads();
                    __threadfence();
                }

                const float* At = Asrc + ((size_t)b * TLEN + (size_t)ci * BM) * DIMX;
                const float* Bt = Wl + (size_t)dir * DIMX * G3 + nt * BN;
                float* Ct = xgdst + (size_t)dir * MROWS * G3 +
                            ((size_t)b * TLEN + (size_t)ci * BM) * G3 + nt * BN;

                unsigned long long acc[2][4];
#pragma unroll
                for (int p = 0; p < 2; p++)
#pragma unroll
                    for (int q = 0; q < 4; q++) acc[p][q] = 0ULL;

                // prologue: load k-chunk 0
                float4 a0r = make_float4(0.f, 0.f, 0.f, 0.f);
                float4 b0r = make_float4(0.f, 0.f, 0.f, 0.f);
                if (tid < 512)
                    a0r = *(const float4*)&At[(size_t)arow * DIMX + ak];
                if (tid < 384)
                    b0r = *(const float4*)&Bt[(size_t)brow * G3 + bc];

                if (tid < 512) {
                    sh_As[0][ak + 0][arow] = a0r.x;
                    sh_As[0][ak + 1][arow] = a0r.y;
                    sh_As[0][ak + 2][arow] = a0r.z;
                    sh_As[0][ak + 3][arow] = a0r.w;
                }
                if (tid < 384) {
                    ulonglong2 bp0, bp1;
                    bp0.x = pk2(b0r.x, b0r.x); bp0.y = pk2(b0r.y, b0r.y);
                    bp1.x = pk2(b0r.z, b0r.z); bp1.y = pk2(b0r.w, b0r.w);
                    *(ulonglong2*)&sh_Bs[0][brow][bc] = bp0;
                    *(ulonglong2*)&sh_Bs[0][brow][bc + 2] = bp1;
                }
                __syncthreads();

                for (int cc = 0; cc < DIMX / BK; cc++) {
                    const int cur = cc & 1;
                    if (cc < DIMX / BK - 1) {
                        const int k0 = (cc + 1) * BK;
                        if (tid < 512)
                            a0r = *(const float4*)&At[(size_t)arow * DIMX + k0 + ak];
                        if (tid < 384)
                            b0r = *(const float4*)&Bt[(size_t)(k0 + brow) * G3 + bc];
                    }
#pragma unroll
                    for (int k = 0; k < BK; k++) {
                        ulonglong2 av = *(const ulonglong2*)&sh_As[cur][k][ty4];
                        const unsigned long long* Bk = &sh_Bs[cur][k][tx4];
                        ulonglong2 bv0 = *(const ulonglong2*)(Bk);
                        ulonglong2 bv1 = *(const ulonglong2*)(Bk + 2);
                        acc[0][0] = fma2(av.x, bv0.x, acc[0][0]);
                        acc[0][1] = fma2(av.x, bv0.y, acc[0][1]);
                        acc[0][2] = fma2(av.x, bv1.x, acc[0][2]);
                        acc[0][3] = fma2(av.x, bv1.y, acc[0][3]);
                        acc[1][0] = fma2(av.y, bv0.x, acc[1][0]);
                        acc[1][1] = fma2(av.y, bv0.y, acc[1][1]);
                        acc[1][2] = fma2(av.y, bv1.x, acc[1][2]);
                        acc[1][3] = fma2(av.y, bv1.y, acc[1][3]);
                    }
                    if (cc < DIMX / BK - 1) {
                        const int nxt = cur ^ 1;
                        __syncthreads();
                        if (tid < 512) {
                            sh_As[nxt][ak + 0][arow] = a0r.x;
                            sh_As[nxt][ak + 1][arow] = a0r.y;
                            sh_As[nxt][ak + 2][arow] = a0r.z;
                            sh_As[nxt][ak + 3][arow] = a0r.w;
                        }
                        if (tid < 384) {
                            ulonglong2 bp0, bp1;
                            bp0.x = pk2(b0r.x, b0r.x); bp0.y = pk2(b0r.y, b0r.y);
                            bp1.x = pk2(b0r.z, b0r.z); bp1.y = pk2(b0r.w, b0r.w);
                            *(ulonglong2*)&sh_Bs[nxt][brow][bc] = bp0;
                            *(ulonglong2*)&sh_Bs[nxt][brow][bc + 2] = bp1;
                        }
                        __syncthreads();
                    }
                }

                // epilogue: rows ty4+2p (lo) and ty4+2p+1 (hi)
#pragma unroll
                for (int p = 0; p < 2; p++) {
                    float l0, h0, l1, h1, l2, h2, l3, h3;
                    up2(acc[p][0], l0, h0);
                    up2(acc[p][1], l1, h1);
                    up2(acc[p][2], l2, h2);
                    up2(acc[p][3], l3, h3);
                    const int row = ty4 + 2 * p;
                    *(float4*)&Ct[(size_t)row * G3 + tx4] =
                        make_float4(l0, l1, l2, l3);
                    *(float4*)&Ct[(size_t)(row + 1) * G3 + tx4] =
                        make_float4(h0, h1, h2, h3);
                }
                __syncthreads();
                if (tid == 0) {
                    __threadfence();
                    atomicAdd(&g_xgready[l][dir][b][ci], 1u);
                }
                __syncthreads();
            }
        }
    }
}

// ---------------------------------------------------------------------------
extern "C" void kernel_launch(void* const* d_in, const int* in_sizes, int n_in,
                              void* d_out, int out_size) {
    const float* x  = (const float*)d_in[0];
    const float* Wi = (const float*)d_in[1];
    const float* Wh = (const float*)d_in[2];
    const float* bh = (const float*)d_in[3];
    float* out = (float*)d_out;

    reset_flags<<<(NLAYER * 2 * BATCH * NCHUNK + 255) / 256, 256>>>();
    fused_birnn<<<NBLK, NTHR>>>(x, Wi, Wh, bh, out);
}